// round 16
// baseline (speedup 1.0000x reference)
#include <cuda_runtime.h>
#include <cstdint>

// out = x * (1 - mask), mask broadcasts over C=3.
// x:    [B=64, C=3, H=512, W=512] f32
// mask: [B=64, 1,   H=512, W=512] f32, exactly 0/1 in large rectangles.
//
// R5 trick: mask==1 -> out exactly 0.0f -> skip x loads.
// R11: 256-bit accesses (ld/st.global.v8.f32), warp = 1024B contiguous.
// R15: PERSISTENT grid-stride kernel -- single wave (148x8 CTAs), each
// thread streams ~7 v8 chunks back-to-back. Eliminates ~9 waves of CTA
// retire/launch transients that drain the store pipe and restart the load
// stream. Index math is all shifts (chunks per image = 2^15).

static constexpr int Cc = 3;
static constexpr int HW = 512 * 512;
static constexpr int HW4 = HW / 4;            // 65536 float4 per plane (2^16)
static constexpr int CHUNKS_PER_IMG = HW4 / 2; // 32768 (2^15) v8 chunks
static constexpr int THREADS = 256;
static constexpr int CTAS = 148 * 8;           // one full wave at ~40 regs

__device__ __forceinline__ void ldg256(const float4* p, float4& a, float4& b) {
    asm volatile("ld.global.v8.f32 {%0,%1,%2,%3,%4,%5,%6,%7}, [%8];"
                 : "=f"(a.x), "=f"(a.y), "=f"(a.z), "=f"(a.w),
                   "=f"(b.x), "=f"(b.y), "=f"(b.z), "=f"(b.w)
                 : "l"(p));
}

__device__ __forceinline__ void stg256(float4* p, float4 a, float4 b) {
    asm volatile("st.global.v8.f32 [%0], {%1,%2,%3,%4,%5,%6,%7,%8};"
                 :: "l"(p),
                    "f"(a.x), "f"(a.y), "f"(a.z), "f"(a.w),
                    "f"(b.x), "f"(b.y), "f"(b.z), "f"(b.w)
                 : "memory");
}

__device__ __forceinline__ float4 blend(float4 xv, float4 m) {
    return make_float4(xv.x * (1.0f - m.x), xv.y * (1.0f - m.y),
                       xv.z * (1.0f - m.z), xv.w * (1.0f - m.w));
}

__device__ __forceinline__ bool allone(float4 m) {
    return (m.x == 1.0f) & (m.y == 1.0f) & (m.z == 1.0f) & (m.w == 1.0f);
}

__global__ __launch_bounds__(THREADS)
void random_mask_kernel(const float4* __restrict__ x,
                        const float4* __restrict__ mask,
                        float4* __restrict__ out,
                        int total_chunks) {
    const int stride = gridDim.x * THREADS;

    for (int c = blockIdx.x * THREADS + threadIdx.x; c < total_chunks; c += stride) {
        const int b = c >> 15;                     // c / CHUNKS_PER_IMG
        const int v = (c & (CHUNKS_PER_IMG - 1)) * 2;  // float4 index in plane

        const long long mi = ((long long)b << 16) + v;              // b*HW4 + v
        const long long x0 = ((long long)(b * Cc) << 16) + v;       // b*3*HW4 + v

        float4 m0, m1;
        ldg256(&mask[mi], m0, m1);

        const float4 z = make_float4(0.0f, 0.0f, 0.0f, 0.0f);

        if (allone(m0) & allone(m1)) {
            stg256(&out[x0],           z, z);
            stg256(&out[x0 + HW4],     z, z);
            stg256(&out[x0 + 2 * HW4], z, z);
            continue;
        }

        float4 a0, a1, b0, b1, c0, c1;
        ldg256(&x[x0],           a0, a1);
        ldg256(&x[x0 + HW4],     b0, b1);
        ldg256(&x[x0 + 2 * HW4], c0, c1);

        stg256(&out[x0],           blend(a0, m0), blend(a1, m1));
        stg256(&out[x0 + HW4],     blend(b0, m0), blend(b1, m1));
        stg256(&out[x0 + 2 * HW4], blend(c0, m0), blend(c1, m1));
    }
}

extern "C" void kernel_launch(void* const* d_in, const int* in_sizes, int n_in,
                              void* d_out, int out_size) {
    const float4* x    = (const float4*)d_in[0];
    const float4* mask = (const float4*)d_in[1];
    float4* out        = (float4*)d_out;

    const int B = in_sizes[1] / HW;                    // 64
    const int total_chunks = B * CHUNKS_PER_IMG;       // 2,097,152
    random_mask_kernel<<<CTAS, THREADS>>>(x, mask, out, total_chunks);
}

// round 17
// speedup vs baseline: 1.0524x; 1.0524x over previous
#include <cuda_runtime.h>
#include <cstdint>

// out = x * (1 - mask), mask broadcasts over C=3.
// x:    [B=64, C=3, H=512, W=512] f32
// mask: [B=64, 1,   H=512, W=512] f32, exactly 0/1 in large rectangles.
//
// FINAL (R11 config — best measured: 53.4us kernel, ~60.5us dur):
//  * mask==1 regions produce exactly 0.0f -> the three x-plane loads are
//    skipped entirely (~45% of x read traffic eliminated for this seed).
//  * 256-bit global accesses (sm_100+ ld/st.global.v8.f32): each thread
//    owns one 32B chunk (two adjacent float4), warp = 1024B contiguous,
//    half the LSU/L1 requests of a float4 kernel.
//  * 256-thread CTAs, grid (posblock=128, batch=64); regs=40, no spills.
// Measured limiter: compulsory 201MB of out-writes at ~3.76TB/s sustained
// HBM write rate (near the write-direction ceiling). Traffic is at floor;
// occupancy/MLP/wave-structure variations were all bandwidth-invariant.

static constexpr int Cc = 3;
static constexpr int HW = 512 * 512;
static constexpr int HW4 = HW / 4;        // 65536 float4 per plane
static constexpr int THREADS = 256;

__device__ __forceinline__ void ldg256(const float4* p, float4& a, float4& b) {
    asm volatile("ld.global.v8.f32 {%0,%1,%2,%3,%4,%5,%6,%7}, [%8];"
                 : "=f"(a.x), "=f"(a.y), "=f"(a.z), "=f"(a.w),
                   "=f"(b.x), "=f"(b.y), "=f"(b.z), "=f"(b.w)
                 : "l"(p));
}

__device__ __forceinline__ void stg256(float4* p, float4 a, float4 b) {
    asm volatile("st.global.v8.f32 [%0], {%1,%2,%3,%4,%5,%6,%7,%8};"
                 :: "l"(p),
                    "f"(a.x), "f"(a.y), "f"(a.z), "f"(a.w),
                    "f"(b.x), "f"(b.y), "f"(b.z), "f"(b.w)
                 : "memory");
}

__device__ __forceinline__ float4 blend(float4 xv, float4 m) {
    return make_float4(xv.x * (1.0f - m.x), xv.y * (1.0f - m.y),
                       xv.z * (1.0f - m.z), xv.w * (1.0f - m.w));
}

__device__ __forceinline__ bool allone(float4 m) {
    return (m.x == 1.0f) & (m.y == 1.0f) & (m.z == 1.0f) & (m.w == 1.0f);
}

__global__ __launch_bounds__(THREADS)
void random_mask_kernel(const float4* __restrict__ x,
                        const float4* __restrict__ mask,
                        float4* __restrict__ out) {
    const int b = blockIdx.y;                                     // batch
    // Two adjacent float4 positions per thread, one v8 access each.
    const int v = (blockIdx.x * THREADS + threadIdx.x) * 2;       // 32B aligned

    const long long mi = (long long)b * HW4 + v;
    const long long x0 = (long long)(b * Cc) * HW4 + v;

    float4 m0, m1;
    ldg256(&mask[mi], m0, m1);

    const bool masked = allone(m0) & allone(m1);

    const float4 z = make_float4(0.0f, 0.0f, 0.0f, 0.0f);

    if (masked) {
        stg256(&out[x0],           z, z);
        stg256(&out[x0 + HW4],     z, z);
        stg256(&out[x0 + 2 * HW4], z, z);
        return;
    }

    float4 a0, a1, b0, b1, c0, c1;
    ldg256(&x[x0],           a0, a1);
    ldg256(&x[x0 + HW4],     b0, b1);
    ldg256(&x[x0 + 2 * HW4], c0, c1);

    stg256(&out[x0],           blend(a0, m0), blend(a1, m1));
    stg256(&out[x0 + HW4],     blend(b0, m0), blend(b1, m1));
    stg256(&out[x0 + 2 * HW4], blend(c0, m0), blend(c1, m1));
}

extern "C" void kernel_launch(void* const* d_in, const int* in_sizes, int n_in,
                              void* d_out, int out_size) {
    const float4* x    = (const float4*)d_in[0];
    const float4* mask = (const float4*)d_in[1];
    float4* out        = (float4*)d_out;

    const int B = in_sizes[1] / HW;                   // 64
    dim3 grid(HW4 / (THREADS * 2), B);                // (128, 64)
    random_mask_kernel<<<grid, THREADS>>>(x, mask, out);
}